// round 9
// baseline (speedup 1.0000x reference)
#include <cuda_runtime.h>
#include <cstdint>
#include <math.h>

#define D_MODEL 1024
#define NHEAD   16
#define DK      64
#define BATCH   2
#define NQ      2048
#define NKV     2048

// Scratch (allocation-free)
__device__ float g_Q[BATCH * NQ * D_MODEL];
__device__ float g_attn[BATCH * NQ * D_MODEL];
__device__ float g_vred[BATCH * NHEAD * DK];

// ----------------------------------------------------------------------------
// Fast exp on the FMA/ALU pipes (no MUFU). Handles -1e9 (mask) -> ~0.
// ----------------------------------------------------------------------------
__device__ __forceinline__ float fexp(float x) {
    float y = x * 1.4426950408889634f;
    y = fmaxf(y, -126.0f);
    float t = y + 12582912.0f;
    float n = t - 12582912.0f;
    float f = y - n;
    float p = 1.3333558e-3f;
    p = fmaf(p, f, 9.6181290e-3f);
    p = fmaf(p, f, 5.5504109e-2f);
    p = fmaf(p, f, 2.4022651e-1f);
    p = fmaf(p, f, 6.9314718e-1f);
    p = fmaf(p, f, 1.0f);
    int e = __float_as_int(t) - 0x4B400000;
    float s = __int_as_float((e + 127) << 23);
    return p * s;
}

__device__ __forceinline__ float to_tf32(float x) {
    float r; asm("cvt.rna.tf32.f32 %0, %1;" : "=f"(r) : "f"(x));
    return r;
}
__device__ __forceinline__ uint32_t tf32u(float x) {
    return __float_as_uint(to_tf32(x));
}

__device__ __forceinline__ void mma_tf32(float* c, const uint32_t* a,
                                         uint32_t b0, uint32_t b1) {
    asm volatile(
        "mma.sync.aligned.m16n8k8.row.col.f32.tf32.tf32.f32 "
        "{%0,%1,%2,%3},{%4,%5,%6,%7},{%8,%9},{%0,%1,%2,%3};"
        : "+f"(c[0]), "+f"(c[1]), "+f"(c[2]), "+f"(c[3])
        : "r"(a[0]), "r"(a[1]), "r"(a[2]), "r"(a[3]), "r"(b0), "r"(b1));
}

__device__ __forceinline__ void cp16(void* smem_dst, const void* gmem_src) {
    unsigned s = (unsigned)__cvta_generic_to_shared(smem_dst);
    asm volatile("cp.async.ca.shared.global [%0], [%1], 16;"
                 :: "r"(s), "l"(__cvta_generic_to_global(gmem_src)) : "memory");
}
#define CP_COMMIT() asm volatile("cp.async.commit_group;" ::: "memory")
#define CP_WAIT0()  asm volatile("cp.async.wait_group 0;"  ::: "memory")

// ----------------------------------------------------------------------------
// Tensor-core GEMM, tf32x3. cp.async raw staging (double-buffered) +
// convert-once: hi in place, lo to single-buffered side arrays.
// Loop order: wait -> sync -> stage(next) -> convert -> sync -> mma.
// stage(next) into buf^1 is issued AFTER the barrier proving all prior-iter
// mma reads of buf^1 finished (fixes R8's WAR race).
// Strides: A 20 (banks 20g+tg), B 136 (banks 8tg+g) -> conflict-free.
// ----------------------------------------------------------------------------
__global__ __launch_bounds__(256, 2) void gemm_tc(const float* __restrict__ A,
                                                  const float* __restrict__ B,
                                                  float* __restrict__ C,
                                                  int M, int N, int K)
{
    __shared__ float Ash[2][128][20];   // raw -> hi (in place)
    __shared__ float Asl[128][20];      // lo (single-buffered)
    __shared__ float Bsh[2][16][136];
    __shared__ float Bsl[16][136];

    const int tid  = threadIdx.x;
    const int warp = tid >> 5;
    const int lane = tid & 31;
    const int g    = lane >> 2;
    const int tg   = lane & 3;
    const int wm   = (warp & 3) * 32;
    const int wn   = (warp >> 2) * 64;
    const int cRow = blockIdx.y * 128;
    const int cCol = blockIdx.x * 128;

    const int ar  = tid >> 2;         // A rows ar, ar+64
    const int ac4 = (tid & 3) * 4;    // A col group
    const int br  = tid >> 5;         // B rows br, br+8
    const int bc4 = (tid & 31) * 4;   // B col group

    float cacc[2][8][4];
#pragma unroll
    for (int mt = 0; mt < 2; mt++)
#pragma unroll
        for (int nt = 0; nt < 8; nt++)
#pragma unroll
            for (int j = 0; j < 4; j++) cacc[mt][nt][j] = 0.f;

    auto stage = [&](int kc, int buf) {
        const int k0 = kc * 16;
        cp16(&Ash[buf][ar][ac4],      &A[(size_t)(cRow + ar) * K + k0 + ac4]);
        cp16(&Ash[buf][ar + 64][ac4], &A[(size_t)(cRow + ar + 64) * K + k0 + ac4]);
        cp16(&Bsh[buf][br][bc4],      &B[(size_t)(k0 + br) * N + cCol + bc4]);
        cp16(&Bsh[buf][br + 8][bc4],  &B[(size_t)(k0 + br + 8) * N + cCol + bc4]);
        CP_COMMIT();
    };

    const int NC = K / 16;
    stage(0, 0);

    for (int kc = 0; kc < NC; kc++) {
        const int buf = kc & 1;
        CP_WAIT0();          // raw chunk kc landed (this thread's copies)
        __syncthreads();     // visible block-wide; all prior-iter mma done

        if (kc + 1 < NC) stage(kc + 1, buf ^ 1);   // overlaps convert+mma below

        // ---- convert once: hi in place, lo to side arrays ----
#pragma unroll
        for (int rr = 0; rr < 2; rr++) {
            int r = ar + rr * 64;
            float4 x = *(float4*)&Ash[buf][r][ac4];
            float4 hv, lv;
            hv.x = to_tf32(x.x); lv.x = to_tf32(x.x - hv.x);
            hv.y = to_tf32(x.y); lv.y = to_tf32(x.y - hv.y);
            hv.z = to_tf32(x.z); lv.z = to_tf32(x.z - hv.z);
            hv.w = to_tf32(x.w); lv.w = to_tf32(x.w - hv.w);
            *(float4*)&Ash[buf][r][ac4] = hv;
            *(float4*)&Asl[r][ac4]      = lv;
        }
#pragma unroll
        for (int rr = 0; rr < 2; rr++) {
            int r = br + rr * 8;
            float4 x = *(float4*)&Bsh[buf][r][bc4];
            float4 hv, lv;
            hv.x = to_tf32(x.x); lv.x = to_tf32(x.x - hv.x);
            hv.y = to_tf32(x.y); lv.y = to_tf32(x.y - hv.y);
            hv.z = to_tf32(x.z); lv.z = to_tf32(x.z - hv.z);
            hv.w = to_tf32(x.w); lv.w = to_tf32(x.w - hv.w);
            *(float4*)&Bsh[buf][r][bc4] = hv;
            *(float4*)&Bsl[r][bc4]      = lv;
        }
        __syncthreads();

        // ---- mma over 2 k-steps of 8 (no conversions) ----
#pragma unroll
        for (int ks = 0; ks < 2; ks++) {
            const int k8 = ks * 8;
            uint32_t ah[2][4], al[2][4];
#pragma unroll
            for (int mt = 0; mt < 2; mt++) {
                int m0 = wm + mt * 16 + g;
                ah[mt][0] = __float_as_uint(Ash[buf][m0][k8 + tg]);
                ah[mt][1] = __float_as_uint(Ash[buf][m0 + 8][k8 + tg]);
                ah[mt][2] = __float_as_uint(Ash[buf][m0][k8 + tg + 4]);
                ah[mt][3] = __float_as_uint(Ash[buf][m0 + 8][k8 + tg + 4]);
                al[mt][0] = __float_as_uint(Asl[m0][k8 + tg]);
                al[mt][1] = __float_as_uint(Asl[m0 + 8][k8 + tg]);
                al[mt][2] = __float_as_uint(Asl[m0][k8 + tg + 4]);
                al[mt][3] = __float_as_uint(Asl[m0 + 8][k8 + tg + 4]);
            }
#pragma unroll
            for (int nt = 0; nt < 8; nt++) {
                int n0 = wn + nt * 8 + g;
                uint32_t bh0 = __float_as_uint(Bsh[buf][k8 + tg][n0]);
                uint32_t bh1 = __float_as_uint(Bsh[buf][k8 + tg + 4][n0]);
                uint32_t bl0 = __float_as_uint(Bsl[k8 + tg][n0]);
                uint32_t bl1 = __float_as_uint(Bsl[k8 + tg + 4][n0]);
#pragma unroll
                for (int mt = 0; mt < 2; mt++) {
                    mma_tf32(cacc[mt][nt], ah[mt], bh0, bh1);
                    mma_tf32(cacc[mt][nt], ah[mt], bl0, bl1);
                    mma_tf32(cacc[mt][nt], al[mt], bh0, bh1);
                }
            }
        }
    }

#pragma unroll
    for (int mt = 0; mt < 2; mt++) {
        int row0 = cRow + wm + mt * 16 + g;
#pragma unroll
        for (int nt = 0; nt < 8; nt++) {
            int col = cCol + wn + nt * 8 + 2 * tg;
            *(float2*)&C[(size_t)row0 * N + col]       = make_float2(cacc[mt][nt][0], cacc[mt][nt][1]);
            *(float2*)&C[(size_t)(row0 + 8) * N + col] = make_float2(cacc[mt][nt][2], cacc[mt][nt][3]);
        }
    }
}

// ----------------------------------------------------------------------------
// Precompute sum(V) over kv per (b,h,d) for the masked-q fallback rows.
// ----------------------------------------------------------------------------
__global__ __launch_bounds__(256) void vred_kernel(const float* __restrict__ V,
                                                   float* __restrict__ out)
{
    const int bh = blockIdx.x;
    const float* Vb = V + (size_t)bh * NKV * DK;
    const int t  = threadIdx.x;
    const int d4 = (t & 15) * 4;
    const int r0 = t >> 4;
    float4 acc = make_float4(0.f, 0.f, 0.f, 0.f);
    for (int r = r0; r < NKV; r += 16) {
        float4 v = *(const float4*)&Vb[(size_t)r * DK + d4];
        acc.x += v.x; acc.y += v.y; acc.z += v.z; acc.w += v.w;
    }
    __shared__ float red[16][64];
    *(float4*)&red[r0][d4] = acc;
    __syncthreads();
    if (t < 64) {
        float s = 0.f;
#pragma unroll
        for (int i = 0; i < 16; i++) s += red[i][t];
        out[bh * DK + t] = s;
    }
}

// ----------------------------------------------------------------------------
// Tensor-core attention (tf32 mma, exp-without-max).
// cp.async raw K/V double-buffered, convert-once in place, race-free ordering.
// ----------------------------------------------------------------------------
struct AttnSmem {
    float    Ks[2][64][68];
    float    Vs[2][64][72];
    uint32_t Ps[128][68];
    float    kvsel[2][64];
    float    sv[64];
};

__global__ __launch_bounds__(256, 2) void attn_mma(
    const float* __restrict__ Q,
    const float* __restrict__ Kin,
    const float* __restrict__ Vin,
    const unsigned* __restrict__ kvmask,
    const unsigned* __restrict__ qmask,
    const float* __restrict__ vred,
    float* __restrict__ attn)
{
    extern __shared__ AttnSmem smem_raw[];
    AttnSmem& s = smem_raw[0];

    const int tid  = threadIdx.x;
    const int warp = tid >> 5;
    const int lane = tid & 31;
    const int g    = lane >> 2;
    const int tg   = lane & 3;
    const int b    = blockIdx.z;
    const int h    = blockIdx.y;
    const int q0   = blockIdx.x * 128;
    const int qb   = warp * 16;

    const float* Kb = Kin + (size_t)(b * NHEAD + h) * NKV * DK;
    const float* Vb = Vin + (size_t)(b * NHEAD + h) * NKV * DK;

    // ---- Q fragments (tf32), resident in regs ----
    uint32_t qf[8][4];
    {
        const float* qp = Q + (size_t)(b * NQ + q0 + qb) * D_MODEL + h * DK;
#pragma unroll
        for (int ks = 0; ks < 8; ks++) {
            qf[ks][0] = tf32u(qp[(size_t)g       * D_MODEL + 8 * ks + tg]);
            qf[ks][1] = tf32u(qp[(size_t)(g + 8) * D_MODEL + 8 * ks + tg]);
            qf[ks][2] = tf32u(qp[(size_t)g       * D_MODEL + 8 * ks + tg + 4]);
            qf[ks][3] = tf32u(qp[(size_t)(g + 8) * D_MODEL + 8 * ks + tg + 4]);
        }
    }

    float of[8][4];
#pragma unroll
    for (int nt = 0; nt < 8; nt++)
#pragma unroll
        for (int j = 0; j < 4; j++) of[nt][j] = 0.f;
    float l0 = 0.f, l1 = 0.f;

    if (tid < 64) s.sv[tid] = vred[(b * NHEAD + h) * DK + tid];

    auto stage = [&](int t, int buf) {
        const int k0 = t * 64;
#pragma unroll
        for (int i = 0; i < 4; i++) {
            int id = tid + i * 256;
            int r = id >> 4, c4 = (id & 15) * 4;
            cp16(&s.Ks[buf][r][c4], &Kb[(size_t)(k0 + r) * DK + c4]);
            cp16(&s.Vs[buf][r][c4], &Vb[(size_t)(k0 + r) * DK + c4]);
        }
        CP_COMMIT();
        if (tid < 64)
            s.kvsel[buf][tid] = (kvmask[b * NKV + k0 + tid] != 0u) ? 0.f : -1e9f;
    };

    const int NT = NKV / 64;
    stage(0, 0);

    for (int t = 0; t < NT; t++) {
        const int buf = t & 1;
        CP_WAIT0();          // raw tile t landed (this thread's copies)
        __syncthreads();     // visible block-wide; all prior-iter mma done

        if (t + 1 < NT) stage(t + 1, buf ^ 1);   // overlaps convert+mma below

        // ---- convert once (in place): raw fp32 -> tf32 ----
#pragma unroll
        for (int i = 0; i < 4; i++) {
            int id = tid + i * 256;
            int r = id >> 4, c4 = (id & 15) * 4;
            float4 k4 = *(float4*)&s.Ks[buf][r][c4];
            k4.x = to_tf32(k4.x); k4.y = to_tf32(k4.y);
            k4.z = to_tf32(k4.z); k4.w = to_tf32(k4.w);
            *(float4*)&s.Ks[buf][r][c4] = k4;
            float4 v4 = *(float4*)&s.Vs[buf][r][c4];
            v4.x = to_tf32(v4.x); v4.y = to_tf32(v4.y);
            v4.z = to_tf32(v4.z); v4.w = to_tf32(v4.w);
            *(float4*)&s.Vs[buf][r][c4] = v4;
        }
        __syncthreads();

        // ---- S = Q K^T ----
        float sc[8][4];
#pragma unroll
        for (int nt = 0; nt < 8; nt++)
#pragma unroll
            for (int j = 0; j < 4; j++) sc[nt][j] = 0.f;
#pragma unroll
        for (int ks = 0; ks < 8; ks++) {
#pragma unroll
            for (int nt = 0; nt < 8; nt++) {
                uint32_t kb0 = __float_as_uint(s.Ks[buf][8 * nt + g][8 * ks + tg]);
                uint32_t kb1 = __float_as_uint(s.Ks[buf][8 * nt + g][8 * ks + tg + 4]);
                mma_tf32(sc[nt], qf[ks], kb0, kb1);
            }
        }

        // ---- epilogue: p = exp(s/8 + sel), accumulate l, store P (tf32) ----
#pragma unroll
        for (int nt = 0; nt < 8; nt++) {
            float s0 = s.kvsel[buf][8 * nt + 2 * tg];
            float s1 = s.kvsel[buf][8 * nt + 2 * tg + 1];
            float p0 = fexp(fmaf(sc[nt][0], 0.125f, s0));
            float p1 = fexp(fmaf(sc[nt][1], 0.125f, s1));
            float p2 = fexp(fmaf(sc[nt][2], 0.125f, s0));
            float p3 = fexp(fmaf(sc[nt][3], 0.125f, s1));
            l0 += p0 + p1;
            l1 += p2 + p3;
            uint2 w0 = make_uint2(tf32u(p0), tf32u(p1));
            uint2 w1 = make_uint2(tf32u(p2), tf32u(p3));
            *(uint2*)&s.Ps[qb + g][8 * nt + 2 * tg]     = w0;
            *(uint2*)&s.Ps[qb + g + 8][8 * nt + 2 * tg] = w1;
        }
        __syncwarp();   // Ps is warp-private

        // ---- O += P V ----
#pragma unroll
        for (int ks = 0; ks < 8; ks++) {
            uint32_t pa[4];
            pa[0] = s.Ps[qb + g][8 * ks + tg];
            pa[1] = s.Ps[qb + g + 8][8 * ks + tg];
            pa[2] = s.Ps[qb + g][8 * ks + tg + 4];
            pa[3] = s.Ps[qb + g + 8][8 * ks + tg + 4];
#pragma unroll
            for (int nt = 0; nt < 8; nt++) {
                uint32_t vb0 = __float_as_uint(s.Vs[buf][8 * ks + tg][8 * nt + g]);
                uint32_t vb1 = __float_as_uint(s.Vs[buf][8 * ks + tg + 4][8 * nt + g]);
                mma_tf32(of[nt], pa, vb0, vb1);
            }
        }
    }

    // ---- l reduction and output ----
    l0 += __shfl_xor_sync(0xffffffffu, l0, 1);
    l0 += __shfl_xor_sync(0xffffffffu, l0, 2);
    l1 += __shfl_xor_sync(0xffffffffu, l1, 1);
    l1 += __shfl_xor_sync(0xffffffffu, l1, 2);
    const float inv0 = 1.f / l0;
    const float inv1 = 1.f / l1;
    const bool qok0 = (qmask[b * NQ + q0 + qb + g]     != 0u);
    const bool qok1 = (qmask[b * NQ + q0 + qb + g + 8] != 0u);
    const float u = 1.f / 2048.f;

    float* op0 = attn + (size_t)(b * NQ + q0 + qb + g)     * D_MODEL + h * DK;
    float* op1 = attn + (size_t)(b * NQ + q0 + qb + g + 8) * D_MODEL + h * DK;
#pragma unroll
    for (int nt = 0; nt < 8; nt++) {
        int d = 8 * nt + 2 * tg;
        float2 o0, o1;
        if (qok0) { o0.x = of[nt][0] * inv0; o0.y = of[nt][1] * inv0; }
        else      { o0.x = s.sv[d] * u;      o0.y = s.sv[d + 1] * u; }
        if (qok1) { o1.x = of[nt][2] * inv1; o1.y = of[nt][3] * inv1; }
        else      { o1.x = s.sv[d] * u;      o1.y = s.sv[d + 1] * u; }
        *(float2*)&op0[d] = o0;
        *(float2*)&op1[d] = o1;
    }
}

// ----------------------------------------------------------------------------
// Inputs (metadata order): x, K, V, Wq, Wo, kv_pad_mask, q_pad_mask
// ----------------------------------------------------------------------------
extern "C" void kernel_launch(void* const* d_in, const int* in_sizes, int n_in,
                              void* d_out, int out_size)
{
    const float*    x   = (const float*)d_in[0];
    const float*    K   = (const float*)d_in[1];
    const float*    V   = (const float*)d_in[2];
    const float*    Wq  = (const float*)d_in[3];
    const float*    Wo  = (const float*)d_in[4];
    const unsigned* kvm = (const unsigned*)d_in[5];
    const unsigned* qm  = (const unsigned*)d_in[6];
    float*          out = (float*)d_out;

    float *gQ, *gA, *gV;
    cudaGetSymbolAddress((void**)&gQ, g_Q);
    cudaGetSymbolAddress((void**)&gA, g_attn);
    cudaGetSymbolAddress((void**)&gV, g_vred);

    const int M = BATCH * NQ;
    dim3 gemm_grid(D_MODEL / 128, M / 128);

    const int ATTN_SMEM = (int)sizeof(AttnSmem);
    cudaFuncSetAttribute(attn_mma, cudaFuncAttributeMaxDynamicSharedMemorySize, ATTN_SMEM);

    gemm_tc<<<gemm_grid, 256>>>(x, Wq, gQ, M, D_MODEL, D_MODEL);

    vred_kernel<<<BATCH * NHEAD, 256>>>(V, gV);

    dim3 attn_grid(NQ / 128, NHEAD, BATCH);
    attn_mma<<<attn_grid, 256, ATTN_SMEM>>>(gQ, K, V, kvm, qm, gV, gA);

    gemm_tc<<<gemm_grid, 256>>>(gA, Wo, out, M, D_MODEL, D_MODEL);
}

// round 11
// speedup vs baseline: 1.2938x; 1.2938x over previous
#include <cuda_runtime.h>
#include <cstdint>
#include <math.h>

#define D_MODEL 1024
#define NHEAD   16
#define DK      64
#define BATCH   2
#define NQ      2048
#define NKV     2048

// Scratch (allocation-free)
__device__ float g_Q[BATCH * NQ * D_MODEL];
__device__ float g_attn[BATCH * NQ * D_MODEL];

// ----------------------------------------------------------------------------
// Fast exp on the FMA/ALU pipes (no MUFU). Handles -1e9 (mask) -> ~0.
// ----------------------------------------------------------------------------
__device__ __forceinline__ float fexp(float x) {
    float y = x * 1.4426950408889634f;
    y = fmaxf(y, -126.0f);
    float t = y + 12582912.0f;
    float n = t - 12582912.0f;
    float f = y - n;
    float p = 1.3333558e-3f;
    p = fmaf(p, f, 9.6181290e-3f);
    p = fmaf(p, f, 5.5504109e-2f);
    p = fmaf(p, f, 2.4022651e-1f);
    p = fmaf(p, f, 6.9314718e-1f);
    p = fmaf(p, f, 1.0f);
    int e = __float_as_int(t) - 0x4B400000;
    float s = __int_as_float((e + 127) << 23);
    return p * s;
}

__device__ __forceinline__ float to_tf32(float x) {
    float r; asm("cvt.rna.tf32.f32 %0, %1;" : "=f"(r) : "f"(x));
    return r;
}
__device__ __forceinline__ uint32_t tf32u(float x) {
    return __float_as_uint(to_tf32(x));
}

// m16n8k8 tf32 mma (sm_80+ path; compiles for plain sm_103)
__device__ __forceinline__ void mma_tf32(float* c, const uint32_t* a,
                                         uint32_t b0, uint32_t b1) {
    asm volatile(
        "mma.sync.aligned.m16n8k8.row.col.f32.tf32.tf32.f32 "
        "{%0,%1,%2,%3},{%4,%5,%6,%7},{%8,%9},{%0,%1,%2,%3};"
        : "+f"(c[0]), "+f"(c[1]), "+f"(c[2]), "+f"(c[3])
        : "r"(a[0]), "r"(a[1]), "r"(a[2]), "r"(a[3]), "r"(b0), "r"(b1));
}

// ----------------------------------------------------------------------------
// Tensor-core GEMM, tf32x2 (A hi/lo split, B tf32-truncated):
//   C = ah*bh + al*bh = (ah+al)*bh ~ A @ tf32(B)
// Error = B truncation only (~2.8e-4 rms), half the mma and B-LDS of tf32x3.
// R6 skeleton: register prefetch, single-buffered smem, split at staging.
// Strides: A 20 (banks 20g+tg), B 136 (banks 8tg+g) -> conflict-free.
// ----------------------------------------------------------------------------
__global__ __launch_bounds__(256, 2) void gemm_tc(const float* __restrict__ A,
                                                  const float* __restrict__ B,
                                                  float* __restrict__ C,
                                                  int M, int N, int K)
{
    __shared__ float Ash[128][20];   // A hi (tf32)
    __shared__ float Asl[128][20];   // A lo (tf32)
    __shared__ float Bsh[16][136];   // B hi (tf32)

    const int tid  = threadIdx.x;
    const int warp = tid >> 5;
    const int lane = tid & 31;
    const int g    = lane >> 2;
    const int tg   = lane & 3;
    const int wm   = (warp & 3) * 32;
    const int wn   = (warp >> 2) * 64;
    const int cRow = blockIdx.y * 128;
    const int cCol = blockIdx.x * 128;

    const int ar  = tid >> 2;         // A rows ar, ar+64
    const int ac4 = (tid & 3) * 4;    // A col group
    const int br  = tid >> 5;         // B rows br, br+8
    const int bc4 = (tid & 31) * 4;   // B col group

    float cacc[2][8][4];
#pragma unroll
    for (int mt = 0; mt < 2; mt++)
#pragma unroll
        for (int nt = 0; nt < 8; nt++)
#pragma unroll
            for (int j = 0; j < 4; j++) cacc[mt][nt][j] = 0.f;

    // prefetch chunk 0
    float4 pa0 = *(const float4*)&A[(size_t)(cRow + ar) * K + ac4];
    float4 pa1 = *(const float4*)&A[(size_t)(cRow + ar + 64) * K + ac4];
    float4 pb0 = *(const float4*)&B[(size_t)br * N + cCol + bc4];
    float4 pb1 = *(const float4*)&B[(size_t)(br + 8) * N + cCol + bc4];

    const int NC = K / 16;
    for (int kc = 0; kc < NC; kc++) {
        // ---- stage: A hi/lo split, B hi only ----
        {
            float h;
            float4 hv, lv;
#define SPLIT4(src, dsth, dstl) \
            h = to_tf32(src.x); hv.x = h; lv.x = to_tf32(src.x - h); \
            h = to_tf32(src.y); hv.y = h; lv.y = to_tf32(src.y - h); \
            h = to_tf32(src.z); hv.z = h; lv.z = to_tf32(src.z - h); \
            h = to_tf32(src.w); hv.w = h; lv.w = to_tf32(src.w - h); \
            *(float4*)&dsth = hv; *(float4*)&dstl = lv;
#define CVT4(src, dsth) \
            hv.x = to_tf32(src.x); hv.y = to_tf32(src.y); \
            hv.z = to_tf32(src.z); hv.w = to_tf32(src.w); \
            *(float4*)&dsth = hv;
            SPLIT4(pa0, Ash[ar][ac4],      Asl[ar][ac4]);
            SPLIT4(pa1, Ash[ar + 64][ac4], Asl[ar + 64][ac4]);
            CVT4(pb0, Bsh[br][bc4]);
            CVT4(pb1, Bsh[br + 8][bc4]);
#undef SPLIT4
#undef CVT4
        }
        __syncthreads();

        // prefetch next chunk while mma runs
        if (kc + 1 < NC) {
            int k0 = (kc + 1) * 16;
            pa0 = *(const float4*)&A[(size_t)(cRow + ar) * K + k0 + ac4];
            pa1 = *(const float4*)&A[(size_t)(cRow + ar + 64) * K + k0 + ac4];
            pb0 = *(const float4*)&B[(size_t)(k0 + br) * N + cCol + bc4];
            pb1 = *(const float4*)&B[(size_t)(k0 + br + 8) * N + cCol + bc4];
        }

        // ---- mma over 2 k-steps of 8 ----
#pragma unroll
        for (int ks = 0; ks < 2; ks++) {
            const int k8 = ks * 8;
            uint32_t ah[2][4], al[2][4];
#pragma unroll
            for (int mt = 0; mt < 2; mt++) {
                int m0 = wm + mt * 16 + g;
                ah[mt][0] = __float_as_uint(Ash[m0][k8 + tg]);
                ah[mt][1] = __float_as_uint(Ash[m0 + 8][k8 + tg]);
                ah[mt][2] = __float_as_uint(Ash[m0][k8 + tg + 4]);
                ah[mt][3] = __float_as_uint(Ash[m0 + 8][k8 + tg + 4]);
                al[mt][0] = __float_as_uint(Asl[m0][k8 + tg]);
                al[mt][1] = __float_as_uint(Asl[m0 + 8][k8 + tg]);
                al[mt][2] = __float_as_uint(Asl[m0][k8 + tg + 4]);
                al[mt][3] = __float_as_uint(Asl[m0 + 8][k8 + tg + 4]);
            }
#pragma unroll
            for (int nt = 0; nt < 8; nt++) {
                int n0 = wn + nt * 8 + g;
                uint32_t bh0 = __float_as_uint(Bsh[k8 + tg][n0]);
                uint32_t bh1 = __float_as_uint(Bsh[k8 + tg + 4][n0]);
#pragma unroll
                for (int mt = 0; mt < 2; mt++) {
                    mma_tf32(cacc[mt][nt], ah[mt], bh0, bh1);
                    mma_tf32(cacc[mt][nt], al[mt], bh0, bh1);
                }
            }
        }
        __syncthreads();
    }

#pragma unroll
    for (int mt = 0; mt < 2; mt++) {
        int row0 = cRow + wm + mt * 16 + g;
#pragma unroll
        for (int nt = 0; nt < 8; nt++) {
            int col = cCol + wn + nt * 8 + 2 * tg;
            *(float2*)&C[(size_t)row0 * N + col]       = make_float2(cacc[mt][nt][0], cacc[mt][nt][1]);
            *(float2*)&C[(size_t)(row0 + 8) * N + col] = make_float2(cacc[mt][nt][2], cacc[mt][nt][3]);
        }
    }
}

// ----------------------------------------------------------------------------
// Tensor-core attention via mma.sync tf32 (exp-without-max). Exact R6 version.
// ----------------------------------------------------------------------------
struct AttnSmem {
    uint32_t Ks[64][68];
    uint32_t Vs[64][72];
    uint32_t Ps[128][68];
    float    kvsel[64];
    float    vred[64];
};

__global__ __launch_bounds__(256, 2) void attn_mma(
    const float* __restrict__ Q,
    const float* __restrict__ Kin,
    const float* __restrict__ Vin,
    const unsigned* __restrict__ kvmask,
    const unsigned* __restrict__ qmask,
    float* __restrict__ attn)
{
    extern __shared__ AttnSmem smem_raw[];
    AttnSmem& s = smem_raw[0];

    const int tid  = threadIdx.x;
    const int warp = tid >> 5;
    const int lane = tid & 31;
    const int g    = lane >> 2;
    const int tg   = lane & 3;
    const int b    = blockIdx.z;
    const int h    = blockIdx.y;
    const int q0   = blockIdx.x * 128;
    const int qb   = warp * 16;

    uint32_t qf[8][4];
    {
        const float* qp = Q + (size_t)(b * NQ + q0 + qb) * D_MODEL + h * DK;
#pragma unroll
        for (int ks = 0; ks < 8; ks++) {
            qf[ks][0] = tf32u(qp[(size_t)g       * D_MODEL + 8 * ks + tg]);
            qf[ks][1] = tf32u(qp[(size_t)(g + 8) * D_MODEL + 8 * ks + tg]);
            qf[ks][2] = tf32u(qp[(size_t)g       * D_MODEL + 8 * ks + tg + 4]);
            qf[ks][3] = tf32u(qp[(size_t)(g + 8) * D_MODEL + 8 * ks + tg + 4]);
        }
    }

    float of[8][4];
#pragma unroll
    for (int nt = 0; nt < 8; nt++)
#pragma unroll
        for (int j = 0; j < 4; j++) of[nt][j] = 0.f;
    float l0 = 0.f, l1 = 0.f;
    float4 vsum = make_float4(0.f, 0.f, 0.f, 0.f);

    if (tid < 64) s.vred[tid] = 0.f;

    const float* Kb = Kin + (size_t)(b * NHEAD + h) * NKV * DK;
    const float* Vb = Vin + (size_t)(b * NHEAD + h) * NKV * DK;
    const int c4 = (tid & 15) * 4;
    const int r0 = tid >> 4;

    for (int t = 0; t < NKV / 64; t++) {
        const int k0 = t * 64;
        __syncthreads();

#pragma unroll
        for (int i = 0; i < 4; i++) {
            int r = r0 + i * 16;
            float4 k4 = *(const float4*)&Kb[(size_t)(k0 + r) * DK + c4];
            uint4 ku = make_uint4(tf32u(k4.x), tf32u(k4.y), tf32u(k4.z), tf32u(k4.w));
            *(uint4*)&s.Ks[r][c4] = ku;
            float4 v4 = *(const float4*)&Vb[(size_t)(k0 + r) * DK + c4];
            vsum.x += v4.x; vsum.y += v4.y; vsum.z += v4.z; vsum.w += v4.w;
            uint4 vu = make_uint4(tf32u(v4.x), tf32u(v4.y), tf32u(v4.z), tf32u(v4.w));
            *(uint4*)&s.Vs[r][c4] = vu;
        }
        if (tid < 64)
            s.kvsel[tid] = (kvmask[b * NKV + k0 + tid] != 0u) ? 0.f : -1e9f;
        __syncthreads();

        float sc[8][4];
#pragma unroll
        for (int nt = 0; nt < 8; nt++)
#pragma unroll
            for (int j = 0; j < 4; j++) sc[nt][j] = 0.f;
#pragma unroll
        for (int ks = 0; ks < 8; ks++) {
#pragma unroll
            for (int nt = 0; nt < 8; nt++) {
                uint32_t kb0 = s.Ks[8 * nt + g][8 * ks + tg];
                uint32_t kb1 = s.Ks[8 * nt + g][8 * ks + tg + 4];
                mma_tf32(sc[nt], qf[ks], kb0, kb1);
            }
        }

#pragma unroll
        for (int nt = 0; nt < 8; nt++) {
            float s0 = s.kvsel[8 * nt + 2 * tg];
            float s1 = s.kvsel[8 * nt + 2 * tg + 1];
            float p0 = fexp(fmaf(sc[nt][0], 0.125f, s0));
            float p1 = fexp(fmaf(sc[nt][1], 0.125f, s1));
            float p2 = fexp(fmaf(sc[nt][2], 0.125f, s0));
            float p3 = fexp(fmaf(sc[nt][3], 0.125f, s1));
            l0 += p0 + p1;
            l1 += p2 + p3;
            uint2 w0 = make_uint2(tf32u(p0), tf32u(p1));
            uint2 w1 = make_uint2(tf32u(p2), tf32u(p3));
            *(uint2*)&s.Ps[qb + g][8 * nt + 2 * tg]     = w0;
            *(uint2*)&s.Ps[qb + g + 8][8 * nt + 2 * tg] = w1;
        }
        __syncwarp();

#pragma unroll
        for (int ks = 0; ks < 8; ks++) {
            uint32_t pa[4];
            pa[0] = s.Ps[qb + g][8 * ks + tg];
            pa[1] = s.Ps[qb + g + 8][8 * ks + tg];
            pa[2] = s.Ps[qb + g][8 * ks + tg + 4];
            pa[3] = s.Ps[qb + g + 8][8 * ks + tg + 4];
#pragma unroll
            for (int nt = 0; nt < 8; nt++) {
                uint32_t vb0 = s.Vs[8 * ks + tg][8 * nt + g];
                uint32_t vb1 = s.Vs[8 * ks + tg + 4][8 * nt + g];
                mma_tf32(of[nt], pa, vb0, vb1);
            }
        }
    }

    atomicAdd(&s.vred[c4 + 0], vsum.x);
    atomicAdd(&s.vred[c4 + 1], vsum.y);
    atomicAdd(&s.vred[c4 + 2], vsum.z);
    atomicAdd(&s.vred[c4 + 3], vsum.w);
    __syncthreads();

    l0 += __shfl_xor_sync(0xffffffffu, l0, 1);
    l0 += __shfl_xor_sync(0xffffffffu, l0, 2);
    l1 += __shfl_xor_sync(0xffffffffu, l1, 1);
    l1 += __shfl_xor_sync(0xffffffffu, l1, 2);
    const float inv0 = 1.f / l0;
    const float inv1 = 1.f / l1;
    const bool qok0 = (qmask[b * NQ + q0 + qb + g]     != 0u);
    const bool qok1 = (qmask[b * NQ + q0 + qb + g + 8] != 0u);
    const float u = 1.f / 2048.f;

    float* op0 = attn + (size_t)(b * NQ + q0 + qb + g)     * D_MODEL + h * DK;
    float* op1 = attn + (size_t)(b * NQ + q0 + qb + g + 8) * D_MODEL + h * DK;
#pragma unroll
    for (int nt = 0; nt < 8; nt++) {
        int d = 8 * nt + 2 * tg;
        float2 o0, o1;
        if (qok0) { o0.x = of[nt][0] * inv0; o0.y = of[nt][1] * inv0; }
        else      { o0.x = s.vred[d] * u;    o0.y = s.vred[d + 1] * u; }
        if (qok1) { o1.x = of[nt][2] * inv1; o1.y = of[nt][3] * inv1; }
        else      { o1.x = s.vred[d] * u;    o1.y = s.vred[d + 1] * u; }
        *(float2*)&op0[d] = o0;
        *(float2*)&op1[d] = o1;
    }
}

// ----------------------------------------------------------------------------
// Inputs (metadata order): x, K, V, Wq, Wo, kv_pad_mask, q_pad_mask
// ----------------------------------------------------------------------------
extern "C" void kernel_launch(void* const* d_in, const int* in_sizes, int n_in,
                              void* d_out, int out_size)
{
    const float*    x   = (const float*)d_in[0];
    const float*    K   = (const float*)d_in[1];
    const float*    V   = (const float*)d_in[2];
    const float*    Wq  = (const float*)d_in[3];
    const float*    Wo  = (const float*)d_in[4];
    const unsigned* kvm = (const unsigned*)d_in[5];
    const unsigned* qm  = (const unsigned*)d_in[6];
    float*          out = (float*)d_out;

    float *gQ, *gA;
    cudaGetSymbolAddress((void**)&gQ, g_Q);
    cudaGetSymbolAddress((void**)&gA, g_attn);

    const int M = BATCH * NQ;
    dim3 gemm_grid(D_MODEL / 128, M / 128);

    const int ATTN_SMEM = (int)sizeof(AttnSmem);
    cudaFuncSetAttribute(attn_mma, cudaFuncAttributeMaxDynamicSharedMemorySize, ATTN_SMEM);

    gemm_tc<<<gemm_grid, 256>>>(x, Wq, gQ, M, D_MODEL, D_MODEL);

    dim3 attn_grid(NQ / 128, NHEAD, BATCH);
    attn_mma<<<attn_grid, 256, ATTN_SMEM>>>(gQ, K, V, kvm, qm, gA);

    gemm_tc<<<gemm_grid, 256>>>(gA, Wo, out, M, D_MODEL, D_MODEL);
}

// round 12
// speedup vs baseline: 1.5885x; 1.2278x over previous
#include <cuda_runtime.h>
#include <cstdint>
#include <math.h>

#define D_MODEL 1024
#define NHEAD   16
#define DK      64
#define BATCH   2
#define NQ      2048
#define NKV     2048

// Scratch (allocation-free)
__device__ float g_Q[BATCH * NQ * D_MODEL];
__device__ float g_attn[BATCH * NQ * D_MODEL];

__device__ __forceinline__ float to_tf32(float x) {
    float r; asm("cvt.rna.tf32.f32 %0, %1;" : "=f"(r) : "f"(x));
    return r;
}
__device__ __forceinline__ uint32_t tf32u(float x) {
    return __float_as_uint(to_tf32(x));
}
__device__ __forceinline__ float ex2f(float x) {
    float r; asm("ex2.approx.f32 %0, %1;" : "=f"(r) : "f"(x)); return r;
}

// m16n8k8 tf32 mma (sm_80+ path; compiles for plain sm_103)
__device__ __forceinline__ void mma_tf32(float* c, const uint32_t* a,
                                         uint32_t b0, uint32_t b1) {
    asm volatile(
        "mma.sync.aligned.m16n8k8.row.col.f32.tf32.tf32.f32 "
        "{%0,%1,%2,%3},{%4,%5,%6,%7},{%8,%9},{%0,%1,%2,%3};"
        : "+f"(c[0]), "+f"(c[1]), "+f"(c[2]), "+f"(c[3])
        : "r"(a[0]), "r"(a[1]), "r"(a[2]), "r"(a[3]), "r"(b0), "r"(b1));
}

// ----------------------------------------------------------------------------
// Tensor-core GEMM, tf32x1 (A and B truncated to tf32, single mma).
// C[M,N] = A[M,K] @ B[K,N] row-major. 128x128 tile, K-chunk 16, 8 warps 4x2.
// R6 skeleton: register prefetch, single-buffered smem, convert at staging.
// Strides: A 20 (banks 20g+tg), B 136 (banks 8tg+g) -> conflict-free.
// ----------------------------------------------------------------------------
__global__ __launch_bounds__(256, 2) void gemm_tc(const float* __restrict__ A,
                                                  const float* __restrict__ B,
                                                  float* __restrict__ C,
                                                  int M, int N, int K)
{
    __shared__ float Ash[128][20];   // A (tf32)
    __shared__ float Bsh[16][136];   // B (tf32)

    const int tid  = threadIdx.x;
    const int warp = tid >> 5;
    const int lane = tid & 31;
    const int g    = lane >> 2;
    const int tg   = lane & 3;
    const int wm   = (warp & 3) * 32;
    const int wn   = (warp >> 2) * 64;
    const int cRow = blockIdx.y * 128;
    const int cCol = blockIdx.x * 128;

    const int ar  = tid >> 2;         // A rows ar, ar+64
    const int ac4 = (tid & 3) * 4;    // A col group
    const int br  = tid >> 5;         // B rows br, br+8
    const int bc4 = (tid & 31) * 4;   // B col group

    float cacc[2][8][4];
#pragma unroll
    for (int mt = 0; mt < 2; mt++)
#pragma unroll
        for (int nt = 0; nt < 8; nt++)
#pragma unroll
            for (int j = 0; j < 4; j++) cacc[mt][nt][j] = 0.f;

    // prefetch chunk 0
    float4 pa0 = *(const float4*)&A[(size_t)(cRow + ar) * K + ac4];
    float4 pa1 = *(const float4*)&A[(size_t)(cRow + ar + 64) * K + ac4];
    float4 pb0 = *(const float4*)&B[(size_t)br * N + cCol + bc4];
    float4 pb1 = *(const float4*)&B[(size_t)(br + 8) * N + cCol + bc4];

    const int NC = K / 16;
    for (int kc = 0; kc < NC; kc++) {
        // ---- stage (tf32 truncate once) ----
        {
            float4 hv;
#define CVT4(src, dsth) \
            hv.x = to_tf32(src.x); hv.y = to_tf32(src.y); \
            hv.z = to_tf32(src.z); hv.w = to_tf32(src.w); \
            *(float4*)&dsth = hv;
            CVT4(pa0, Ash[ar][ac4]);
            CVT4(pa1, Ash[ar + 64][ac4]);
            CVT4(pb0, Bsh[br][bc4]);
            CVT4(pb1, Bsh[br + 8][bc4]);
#undef CVT4
        }
        __syncthreads();

        // prefetch next chunk while mma runs
        if (kc + 1 < NC) {
            int k0 = (kc + 1) * 16;
            pa0 = *(const float4*)&A[(size_t)(cRow + ar) * K + k0 + ac4];
            pa1 = *(const float4*)&A[(size_t)(cRow + ar + 64) * K + k0 + ac4];
            pb0 = *(const float4*)&B[(size_t)(k0 + br) * N + cCol + bc4];
            pb1 = *(const float4*)&B[(size_t)(k0 + br + 8) * N + cCol + bc4];
        }

        // ---- mma over 2 k-steps of 8 ----
#pragma unroll
        for (int ks = 0; ks < 2; ks++) {
            const int k8 = ks * 8;
            uint32_t ah[2][4];
#pragma unroll
            for (int mt = 0; mt < 2; mt++) {
                int m0 = wm + mt * 16 + g;
                ah[mt][0] = __float_as_uint(Ash[m0][k8 + tg]);
                ah[mt][1] = __float_as_uint(Ash[m0 + 8][k8 + tg]);
                ah[mt][2] = __float_as_uint(Ash[m0][k8 + tg + 4]);
                ah[mt][3] = __float_as_uint(Ash[m0 + 8][k8 + tg + 4]);
            }
#pragma unroll
            for (int nt = 0; nt < 8; nt++) {
                int n0 = wn + nt * 8 + g;
                uint32_t bh0 = __float_as_uint(Bsh[k8 + tg][n0]);
                uint32_t bh1 = __float_as_uint(Bsh[k8 + tg + 4][n0]);
#pragma unroll
                for (int mt = 0; mt < 2; mt++)
                    mma_tf32(cacc[mt][nt], ah[mt], bh0, bh1);
            }
        }
        __syncthreads();
    }

#pragma unroll
    for (int mt = 0; mt < 2; mt++) {
        int row0 = cRow + wm + mt * 16 + g;
#pragma unroll
        for (int nt = 0; nt < 8; nt++) {
            int col = cCol + wn + nt * 8 + 2 * tg;
            *(float2*)&C[(size_t)row0 * N + col]       = make_float2(cacc[mt][nt][0], cacc[mt][nt][1]);
            *(float2*)&C[(size_t)(row0 + 8) * N + col] = make_float2(cacc[mt][nt][2], cacc[mt][nt][3]);
        }
    }
}

// ----------------------------------------------------------------------------
// Tensor-core attention via mma.sync tf32 (exp-without-max).
// R6 structure; epilogue uses 1 FMA + 1 MUFU ex2 per score.
// ----------------------------------------------------------------------------
struct AttnSmem {
    uint32_t Ks[64][68];
    uint32_t Vs[64][72];
    uint32_t Ps[128][68];
    float    kvsel[64];
    float    vred[64];
};

__global__ __launch_bounds__(256, 2) void attn_mma(
    const float* __restrict__ Q,
    const float* __restrict__ Kin,
    const float* __restrict__ Vin,
    const unsigned* __restrict__ kvmask,
    const unsigned* __restrict__ qmask,
    float* __restrict__ attn)
{
    extern __shared__ AttnSmem smem_raw[];
    AttnSmem& s = smem_raw[0];

    const int tid  = threadIdx.x;
    const int warp = tid >> 5;
    const int lane = tid & 31;
    const int g    = lane >> 2;
    const int tg   = lane & 3;
    const int b    = blockIdx.z;
    const int h    = blockIdx.y;
    const int q0   = blockIdx.x * 128;
    const int qb   = warp * 16;
    const float C2 = 0.18033688011112042f;   // 0.125 * log2(e)

    uint32_t qf[8][4];
    {
        const float* qp = Q + (size_t)(b * NQ + q0 + qb) * D_MODEL + h * DK;
#pragma unroll
        for (int ks = 0; ks < 8; ks++) {
            qf[ks][0] = tf32u(qp[(size_t)g       * D_MODEL + 8 * ks + tg]);
            qf[ks][1] = tf32u(qp[(size_t)(g + 8) * D_MODEL + 8 * ks + tg]);
            qf[ks][2] = tf32u(qp[(size_t)g       * D_MODEL + 8 * ks + tg + 4]);
            qf[ks][3] = tf32u(qp[(size_t)(g + 8) * D_MODEL + 8 * ks + tg + 4]);
        }
    }

    float of[8][4];
#pragma unroll
    for (int nt = 0; nt < 8; nt++)
#pragma unroll
        for (int j = 0; j < 4; j++) of[nt][j] = 0.f;
    float l0 = 0.f, l1 = 0.f;
    float4 vsum = make_float4(0.f, 0.f, 0.f, 0.f);

    if (tid < 64) s.vred[tid] = 0.f;

    const float* Kb = Kin + (size_t)(b * NHEAD + h) * NKV * DK;
    const float* Vb = Vin + (size_t)(b * NHEAD + h) * NKV * DK;
    const int c4 = (tid & 15) * 4;
    const int r0 = tid >> 4;

    for (int t = 0; t < NKV / 64; t++) {
        const int k0 = t * 64;
        __syncthreads();

#pragma unroll
        for (int i = 0; i < 4; i++) {
            int r = r0 + i * 16;
            float4 k4 = *(const float4*)&Kb[(size_t)(k0 + r) * DK + c4];
            uint4 ku = make_uint4(tf32u(k4.x), tf32u(k4.y), tf32u(k4.z), tf32u(k4.w));
            *(uint4*)&s.Ks[r][c4] = ku;
            float4 v4 = *(const float4*)&Vb[(size_t)(k0 + r) * DK + c4];
            vsum.x += v4.x; vsum.y += v4.y; vsum.z += v4.z; vsum.w += v4.w;
            uint4 vu = make_uint4(tf32u(v4.x), tf32u(v4.y), tf32u(v4.z), tf32u(v4.w));
            *(uint4*)&s.Vs[r][c4] = vu;
        }
        if (tid < 64)
            s.kvsel[tid] = (kvmask[b * NKV + k0 + tid] != 0u) ? 0.f : -1e9f;
        __syncthreads();

        float sc[8][4];
#pragma unroll
        for (int nt = 0; nt < 8; nt++)
#pragma unroll
            for (int j = 0; j < 4; j++) sc[nt][j] = 0.f;
#pragma unroll
        for (int ks = 0; ks < 8; ks++) {
#pragma unroll
            for (int nt = 0; nt < 8; nt++) {
                uint32_t kb0 = s.Ks[8 * nt + g][8 * ks + tg];
                uint32_t kb1 = s.Ks[8 * nt + g][8 * ks + tg + 4];
                mma_tf32(sc[nt], qf[ks], kb0, kb1);
            }
        }

        // ---- epilogue: p = 2^(s*C2 + sel), accumulate l, store P (tf32) ----
#pragma unroll
        for (int nt = 0; nt < 8; nt++) {
            float s0 = s.kvsel[8 * nt + 2 * tg];
            float s1 = s.kvsel[8 * nt + 2 * tg + 1];
            float p0 = ex2f(fmaf(sc[nt][0], C2, s0));
            float p1 = ex2f(fmaf(sc[nt][1], C2, s1));
            float p2 = ex2f(fmaf(sc[nt][2], C2, s0));
            float p3 = ex2f(fmaf(sc[nt][3], C2, s1));
            l0 += p0 + p1;
            l1 += p2 + p3;
            uint2 w0 = make_uint2(tf32u(p0), tf32u(p1));
            uint2 w1 = make_uint2(tf32u(p2), tf32u(p3));
            *(uint2*)&s.Ps[qb + g][8 * nt + 2 * tg]     = w0;
            *(uint2*)&s.Ps[qb + g + 8][8 * nt + 2 * tg] = w1;
        }
        __syncwarp();   // Ps is warp-private

#pragma unroll
        for (int ks = 0; ks < 8; ks++) {
            uint32_t pa[4];
            pa[0] = s.Ps[qb + g][8 * ks + tg];
            pa[1] = s.Ps[qb + g + 8][8 * ks + tg];
            pa[2] = s.Ps[qb + g][8 * ks + tg + 4];
            pa[3] = s.Ps[qb + g + 8][8 * ks + tg + 4];
#pragma unroll
            for (int nt = 0; nt < 8; nt++) {
                uint32_t vb0 = s.Vs[8 * ks + tg][8 * nt + g];
                uint32_t vb1 = s.Vs[8 * ks + tg + 4][8 * nt + g];
                mma_tf32(of[nt], pa, vb0, vb1);
            }
        }
    }

    atomicAdd(&s.vred[c4 + 0], vsum.x);
    atomicAdd(&s.vred[c4 + 1], vsum.y);
    atomicAdd(&s.vred[c4 + 2], vsum.z);
    atomicAdd(&s.vred[c4 + 3], vsum.w);
    __syncthreads();

    l0 += __shfl_xor_sync(0xffffffffu, l0, 1);
    l0 += __shfl_xor_sync(0xffffffffu, l0, 2);
    l1 += __shfl_xor_sync(0xffffffffu, l1, 1);
    l1 += __shfl_xor_sync(0xffffffffu, l1, 2);
    const float inv0 = 1.f / l0;
    const float inv1 = 1.f / l1;
    const bool qok0 = (qmask[b * NQ + q0 + qb + g]     != 0u);
    const bool qok1 = (qmask[b * NQ + q0 + qb + g + 8] != 0u);
    const float u = 1.f / 2048.f;

    float* op0 = attn + (size_t)(b * NQ + q0 + qb + g)     * D_MODEL + h * DK;
    float* op1 = attn + (size_t)(b * NQ + q0 + qb + g + 8) * D_MODEL + h * DK;
#pragma unroll
    for (int nt = 0; nt < 8; nt++) {
        int d = 8 * nt + 2 * tg;
        float2 o0, o1;
        if (qok0) { o0.x = of[nt][0] * inv0; o0.y = of[nt][1] * inv0; }
        else      { o0.x = s.vred[d] * u;    o0.y = s.vred[d + 1] * u; }
        if (qok1) { o1.x = of[nt][2] * inv1; o1.y = of[nt][3] * inv1; }
        else      { o1.x = s.vred[d] * u;    o1.y = s.vred[d + 1] * u; }
        *(float2*)&op0[d] = o0;
        *(float2*)&op1[d] = o1;
    }
}

// ----------------------------------------------------------------------------
// Inputs (metadata order): x, K, V, Wq, Wo, kv_pad_mask, q_pad_mask
// ----------------------------------------------------------------------------
extern "C" void kernel_launch(void* const* d_in, const int* in_sizes, int n_in,
                              void* d_out, int out_size)
{
    const float*    x   = (const float*)d_in[0];
    const float*    K   = (const float*)d_in[1];
    const float*    V   = (const float*)d_in[2];
    const float*    Wq  = (const float*)d_in[3];
    const float*    Wo  = (const float*)d_in[4];
    const unsigned* kvm = (const unsigned*)d_in[5];
    const unsigned* qm  = (const unsigned*)d_in[6];
    float*          out = (float*)d_out;

    float *gQ, *gA;
    cudaGetSymbolAddress((void**)&gQ, g_Q);
    cudaGetSymbolAddress((void**)&gA, g_attn);

    const int M = BATCH * NQ;
    dim3 gemm_grid(D_MODEL / 128, M / 128);

    const int ATTN_SMEM = (int)sizeof(AttnSmem);
    cudaFuncSetAttribute(attn_mma, cudaFuncAttributeMaxDynamicSharedMemorySize, ATTN_SMEM);

    gemm_tc<<<gemm_grid, 256>>>(x, Wq, gQ, M, D_MODEL, D_MODEL);

    dim3 attn_grid(NQ / 128, NHEAD, BATCH);
    attn_mma<<<attn_grid, 256, ATTN_SMEM>>>(gQ, K, V, kvm, qm, gA);

    gemm_tc<<<gemm_grid, 256>>>(gA, Wo, out, M, D_MODEL, D_MODEL);
}